// round 4
// baseline (speedup 1.0000x reference)
#include <cuda_runtime.h>
#include <cstdint>

#define NN 100000
#define NE 1600000

// ---------------- scratch (device globals: no allocation allowed) ----------------
__device__ float g_Pd[NN * 64];     // x @ W1[0:64]   + b1   (gathered by dst)
__device__ float g_Ps[NN * 64];     // x @ W1[64:128]        (gathered by src)
__device__ float g_agg[NN * 64];    // segment-sum accumulator
__device__ float g_zp[NN * 64];     // pre-BN activations
__device__ float g_stats[128];      // [0:64) column sums, [64:128) column sumsq
__device__ int   g_is64;            // edge_index dtype flag

__device__ __forceinline__ float prelu(float v, float a) { return v >= 0.f ? v : a * v; }

// ---------------- detect edge_index dtype (int64 vs int32) ----------------
__global__ void k_detect(const long long* ei) {
    if (threadIdx.x == 0) {
        int ok = 1;
        for (int i = 0; i < 64; i++) {
            long long v = ei[i];
            if (v < 0 || v >= NN) { ok = 0; break; }
        }
        g_is64 = ok;   // int32 data reinterpreted as int64 fails range check w.p. ~1
    }
}

// ---------------- zero agg + stats ----------------
__global__ void k_zero() {
    int i = blockIdx.x * blockDim.x + threadIdx.x;
    int stride = gridDim.x * blockDim.x;
    for (; i < NN * 64; i += stride) g_agg[i] = 0.f;
    if (blockIdx.x == 0 && threadIdx.x < 128) g_stats[threadIdx.x] = 0.f;
}

// ---------------- node pre-GEMM: Pd / Ps ----------------
// block = 256 threads, 16 nodes/block, 128 outputs per node (Pd|Ps combined)
__global__ void __launch_bounds__(256) k_node_pre(const float* __restrict__ x,
                                                  const float* __restrict__ W1,
                                                  const float* __restrict__ b1) {
    __shared__ float Ws[64 * 128];   // Ws[k*128 + jc]: jc<64 -> W1[k][jc], else W1[64+k][jc-64]
    __shared__ float xs[16 * 65];
    int t = threadIdx.x;
    int nb = blockIdx.x * 16;

    for (int idx = t; idx < 64 * 128; idx += 256) {
        int k = idx >> 7, jc = idx & 127;
        Ws[idx] = (jc < 64) ? W1[k * 64 + jc] : W1[(64 + k) * 64 + (jc - 64)];
    }
    for (int idx = t; idx < 16 * 64; idx += 256) {
        int n = idx >> 6, k = idx & 63;
        xs[n * 65 + k] = x[(nb + n) * 64 + k];
    }
    __syncthreads();

    int node = t & 15;       // lanes 0..15 / 16..31: nodes; jg differs per half-warp
    int jg   = t >> 4;       // 0..15 -> jc = jg*8
    float acc[8];
#pragma unroll
    for (int i = 0; i < 8; i++) acc[i] = 0.f;
#pragma unroll
    for (int k = 0; k < 64; k++) {
        float xv = xs[node * 65 + k];
        const float4* w4 = (const float4*)(Ws + k * 128 + jg * 8);
        float4 wa = w4[0], wb = w4[1];
        acc[0] += xv * wa.x; acc[1] += xv * wa.y; acc[2] += xv * wa.z; acc[3] += xv * wa.w;
        acc[4] += xv * wb.x; acc[5] += xv * wb.y; acc[6] += xv * wb.z; acc[7] += xv * wb.w;
    }
    int gnode = nb + node;
    int jc = jg * 8;
    if (jc < 64) {
#pragma unroll
        for (int i = 0; i < 8; i++) g_Pd[gnode * 64 + jc + i] = acc[i] + b1[jc + i];
    } else {
        int jj = jc - 64;
#pragma unroll
        for (int i = 0; i < 8; i++) g_Ps[gnode * 64 + jj + i] = acc[i];
    }
}

// ---------------- edge kernel: gather -> prelu -> h1@W2 -> prelu -> red.v4 ----------------
// 256 threads = 256 edges per block. Warp-cooperative coalesced gather staged in smem,
// then per-thread 64x64 dot via packed fma.rn.f32x2 with W2^T broadcast from smem.
__global__ void __launch_bounds__(256, 2) k_edge(const void* eiv,
                                                 const float* __restrict__ W2,
                                                 const float* __restrict__ b2,
                                                 const float* __restrict__ A1,
                                                 const float* __restrict__ A2) {
    extern __shared__ float sm[];
    float* w2t = sm;          // 4096 floats: w2t[j*64+k] = W2[k][j]
    float* b2s = sm + 4096;   // 64
    float* hs  = sm + 4160;   // 8 warps * 32 edges * 66 floats

    int t = threadIdx.x;
    for (int idx = t; idx < 4096; idx += 256) {
        int j = idx & 63, k = idx >> 6;
        w2t[j * 64 + k] = W2[k * 64 + j];   // coalesced read, strided smem write (one-time)
    }
    if (t < 64) b2s[t] = b2[t];
    float a1 = A1[0], a2 = A2[0];

    int e = blockIdx.x * 256 + t;           // grid = NE/256 exactly
    long long my_src, my_dst;
    if (g_is64) {
        const long long* ei = (const long long*)eiv;
        my_src = ei[e];
        my_dst = ei[NE + e];
    } else {
        const int* ei = (const int*)eiv;
        my_src = (long long)ei[e];
        my_dst = (long long)ei[NE + e];
    }
    __syncthreads();

    int lane = t & 31;
    float* hsw = hs + (t >> 5) * (32 * 66);

    // Cooperative gather: each iteration the whole warp loads one edge's 64-wide
    // Pd[dst] + Ps[src] rows coalesced (2x LDG.64/lane), applies prelu, stages to smem.
#pragma unroll 1
    for (int ee = 0; ee < 32; ee++) {
        long long d = __shfl_sync(0xffffffffu, my_dst, ee);
        long long s = __shfl_sync(0xffffffffu, my_src, ee);
        const float2* pd2 = (const float2*)(g_Pd + d * 64);
        const float2* ps2 = (const float2*)(g_Ps + s * 64);
        float2 a = pd2[lane];
        float2 b = ps2[lane];
        float v0 = prelu(a.x + b.x, a1);
        float v1 = prelu(a.y + b.y, a1);
        ((float2*)(hsw + ee * 66))[lane] = make_float2(v0, v1);
    }
    __syncwarp();

    // Pull this thread's h1 row into packed f32x2 registers.
    unsigned long long hp[32];
    const float2* hrow = (const float2*)(hsw + lane * 66);
#pragma unroll
    for (int k2 = 0; k2 < 32; k2++) {
        float2 v = hrow[k2];
        asm("mov.b64 %0, {%1, %2};" : "=l"(hp[k2]) : "f"(v.x), "f"(v.y));
    }

    float* aggp = g_agg + my_dst * 64;
#pragma unroll 1
    for (int j4 = 0; j4 < 16; j4++) {
        float r[4];
#pragma unroll
        for (int jj = 0; jj < 4; jj++) {
            int j = j4 * 4 + jj;
            const unsigned long long* w = (const unsigned long long*)(w2t + j * 64);
            unsigned long long acc = 0ULL;   // {0.f, 0.f}
#pragma unroll
            for (int k2 = 0; k2 < 32; k2++)
                asm("fma.rn.f32x2 %0, %1, %2, %0;" : "+l"(acc) : "l"(hp[k2]), "l"(w[k2]));
            float lo, hi;
            asm("mov.b64 {%0, %1}, %2;" : "=f"(lo), "=f"(hi) : "l"(acc));
            r[jj] = prelu(lo + hi + b2s[j], a2);
        }
        asm volatile("red.global.add.v4.f32 [%0], {%1, %2, %3, %4};" ::
                     "l"(aggp + j4 * 4), "f"(r[0]), "f"(r[1]), "f"(r[2]), "f"(r[3]));
    }
}

// ---------------- node MLP + block prelu + BN partial stats ----------------
// block = 256 threads, 32 nodes/block. All lanes of a warp share the same output
// group -> weight smem loads are pure broadcast; node tile reads conflict-free.
__global__ void __launch_bounds__(256) k_node(const float* __restrict__ x,
                                              const float* __restrict__ W3,
                                              const float* __restrict__ b3,
                                              const float* __restrict__ A3,
                                              const float* __restrict__ W4,
                                              const float* __restrict__ b4,
                                              const float* __restrict__ Ablk) {
    extern __shared__ float sm[];
    float* ms  = sm;                         // 32*129
    float* W3s = sm + 4128;                  // 128*64
    float* W4s = sm + 4128 + 8192;           // 64*64
    float* z1s = sm + 4128 + 8192 + 4096;    // 32*65

    int t = threadIdx.x;
    int nb = blockIdx.x * 32;
    for (int idx = t; idx < 8192; idx += 256) W3s[idx] = W3[idx];
    for (int idx = t; idx < 4096; idx += 256) W4s[idx] = W4[idx];
    for (int idx = t; idx < 2048; idx += 256) {
        int n = idx >> 6, k = idx & 63;
        ms[n * 129 + k]      = x[(nb + n) * 64 + k];
        ms[n * 129 + 64 + k] = g_agg[(nb + n) * 64 + k];
    }
    float a3 = A3[0], ab = Ablk[0];
    __syncthreads();

    int node = t & 31;
    int jg   = t >> 5;   // 0..7
    float acc[8];
#pragma unroll
    for (int i = 0; i < 8; i++) acc[i] = 0.f;
#pragma unroll 8
    for (int k = 0; k < 128; k++) {
        float mv = ms[node * 129 + k];
        const float4* w4p = (const float4*)(W3s + k * 64 + jg * 8);
        float4 wa = w4p[0], wb = w4p[1];
        acc[0] += mv * wa.x; acc[1] += mv * wa.y; acc[2] += mv * wa.z; acc[3] += mv * wa.w;
        acc[4] += mv * wb.x; acc[5] += mv * wb.y; acc[6] += mv * wb.z; acc[7] += mv * wb.w;
    }
#pragma unroll
    for (int i = 0; i < 8; i++)
        z1s[node * 65 + jg * 8 + i] = prelu(acc[i] + b3[jg * 8 + i], a3);
    __syncthreads();

#pragma unroll
    for (int i = 0; i < 8; i++) acc[i] = 0.f;
#pragma unroll 8
    for (int k = 0; k < 64; k++) {
        float zv = z1s[node * 65 + k];
        const float4* w4p = (const float4*)(W4s + k * 64 + jg * 8);
        float4 wa = w4p[0], wb = w4p[1];
        acc[0] += zv * wa.x; acc[1] += zv * wa.y; acc[2] += zv * wa.z; acc[3] += zv * wa.w;
        acc[4] += zv * wb.x; acc[5] += zv * wb.y; acc[6] += zv * wb.z; acc[7] += zv * wb.w;
    }

    float zp[8], sq[8];
#pragma unroll
    for (int i = 0; i < 8; i++) {
        zp[i] = prelu(acc[i] + b4[jg * 8 + i], ab);
        sq[i] = zp[i] * zp[i];
    }
    int gnode = nb + node;
    float4* o4 = (float4*)(g_zp + gnode * 64 + jg * 8);
    o4[0] = make_float4(zp[0], zp[1], zp[2], zp[3]);
    o4[1] = make_float4(zp[4], zp[5], zp[6], zp[7]);

    // warp butterfly over the 32 nodes (lanes) -> column partial sums
    float s[8];
#pragma unroll
    for (int i = 0; i < 8; i++) s[i] = zp[i];
#pragma unroll
    for (int o = 16; o > 0; o >>= 1) {
#pragma unroll
        for (int i = 0; i < 8; i++) {
            s[i]  += __shfl_xor_sync(0xffffffffu, s[i], o);
            sq[i] += __shfl_xor_sync(0xffffffffu, sq[i], o);
        }
    }
    if ((t & 31) == 0) {
        int j = jg * 8;
#pragma unroll
        for (int i = 0; i < 8; i++) {
            atomicAdd(&g_stats[j + i], s[i]);
            atomicAdd(&g_stats[64 + j + i], sq[i]);
        }
    }
}

// ---------------- BN finalize ----------------
__global__ void __launch_bounds__(256) k_finalize(const float* __restrict__ gamma,
                                                  const float* __restrict__ beta,
                                                  float* __restrict__ out) {
    int i0 = blockIdx.x * blockDim.x + threadIdx.x;
    int stride = gridDim.x * blockDim.x;   // 65536, multiple of 64 -> j fixed per thread
    int j = i0 & 63;
    const float invN = 1.0f / NN;
    float mean  = g_stats[j] * invN;
    float var   = g_stats[64 + j] * invN - mean * mean;
    float scale = rsqrtf(var + 1e-5f) * gamma[j];
    float bias  = beta[j] - mean * scale;
    for (int i = i0; i < NN * 64; i += stride)
        out[i] = g_zp[i] * scale + bias;
}

// ---------------- launch ----------------
extern "C" void kernel_launch(void* const* d_in, const int* in_sizes, int n_in,
                              void* d_out, int out_size) {
    const float* x     = (const float*)d_in[0];
    const void*  ei    = d_in[1];
    const float* W1    = (const float*)d_in[2];
    const float* b1    = (const float*)d_in[3];
    const float* a1    = (const float*)d_in[4];
    const float* W2    = (const float*)d_in[5];
    const float* b2    = (const float*)d_in[6];
    const float* a2    = (const float*)d_in[7];
    const float* W3    = (const float*)d_in[8];
    const float* b3    = (const float*)d_in[9];
    const float* a3    = (const float*)d_in[10];
    const float* W4    = (const float*)d_in[11];
    const float* b4    = (const float*)d_in[12];
    const float* ablk  = (const float*)d_in[13];
    const float* gamma = (const float*)d_in[14];
    const float* beta  = (const float*)d_in[15];
    float* out = (float*)d_out;

    const int EDGE_SMEM = (4160 + 8 * 32 * 66) * 4;                 // 84224 B
    const int NODE_SMEM = (4128 + 8192 + 4096 + 32 * 65) * 4;       // 73984 B
    cudaFuncSetAttribute(k_edge, cudaFuncAttributeMaxDynamicSharedMemorySize, EDGE_SMEM);
    cudaFuncSetAttribute(k_node, cudaFuncAttributeMaxDynamicSharedMemorySize, NODE_SMEM);

    k_detect<<<1, 32>>>((const long long*)ei);
    k_zero<<<2048, 256>>>();
    k_node_pre<<<NN / 16, 256>>>(x, W1, b1);                  // 6250 blocks (exact)
    k_edge<<<NE / 256, 256, EDGE_SMEM>>>(ei, W2, b2, a1, a2); // 6250 blocks (exact)
    k_node<<<NN / 32, 256, NODE_SMEM>>>(x, W3, b3, a3, W4, b4, ablk); // 3125 blocks (exact)
    k_finalize<<<256, 256>>>(gamma, beta, out);
}

// round 6
// speedup vs baseline: 1.0001x; 1.0001x over previous
#include <cuda_runtime.h>
#include <cstdint>

#define NN 100000
#define NE 1600000

// ---------------- scratch (device globals: no allocation allowed) ----------------
__device__ float g_Pd[NN * 64];     // x @ W1[0:64]   + b1   (gathered by dst)
__device__ float g_Ps[NN * 64];     // x @ W1[64:128]        (gathered by src)
__device__ float g_agg[NN * 64];    // segment-sum accumulator
__device__ float g_zp[NN * 64];     // pre-BN activations
__device__ float g_stats[128];      // [0:64) column sums, [64:128) column sumsq
__device__ int   g_is64;            // edge_index dtype flag

__device__ __forceinline__ float prelu(float v, float a) { return v >= 0.f ? v : a * v; }

// ---------------- detect edge_index dtype (int64 vs int32) ----------------
__global__ void k_detect(const long long* ei) {
    if (threadIdx.x == 0) {
        int ok = 1;
        for (int i = 0; i < 64; i++) {
            long long v = ei[i];
            if (v < 0 || v >= NN) { ok = 0; break; }
        }
        g_is64 = ok;   // int32 data reinterpreted as int64 fails range check w.p. ~1
    }
}

// ---------------- zero agg + stats ----------------
__global__ void k_zero() {
    int i = blockIdx.x * blockDim.x + threadIdx.x;
    int stride = gridDim.x * blockDim.x;
    for (; i < NN * 64; i += stride) g_agg[i] = 0.f;
    if (blockIdx.x == 0 && threadIdx.x < 128) g_stats[threadIdx.x] = 0.f;
}

// ---------------- node pre-GEMM: Pd / Ps (k-pair packed weights, f32x2 math) ------
// block = 256 threads, 16 nodes/block, 128 outputs per node (Pd|Ps combined).
// Wp[(k/2)*256 + jc*2 + (k&1)] = W1cat[k][jc]  -> per k2: 1 LDS.64 + 4 LDS.128 + 8 FFMA2
__global__ void __launch_bounds__(256) k_node_pre(const float* __restrict__ x,
                                                  const float* __restrict__ W1,
                                                  const float* __restrict__ b1) {
    __shared__ float Wp[32 * 256];   // 8192 floats, packed k-pairs
    __shared__ float xs[16 * 66];
    int t = threadIdx.x;
    int nb = blockIdx.x * 16;

    for (int idx = t; idx < 8192; idx += 256) {
        int k = idx >> 7, jc = idx & 127;
        float w = (jc < 64) ? W1[k * 64 + jc] : W1[(64 + k) * 64 + (jc - 64)];
        Wp[(k >> 1) * 256 + jc * 2 + (k & 1)] = w;
    }
    for (int idx = t; idx < 16 * 64; idx += 256) {
        int n = idx >> 6, k = idx & 63;
        xs[n * 66 + k] = x[(nb + n) * 64 + k];
    }
    __syncthreads();

    int node = t & 15;
    int jg   = t >> 4;       // 0..15 -> jc = jg*8
    unsigned long long acc[8];
#pragma unroll
    for (int i = 0; i < 8; i++) acc[i] = 0ULL;

    const float2* xrow = (const float2*)(xs + node * 66);
#pragma unroll
    for (int k2 = 0; k2 < 32; k2++) {
        float2 xv = xrow[k2];
        unsigned long long xp;
        asm("mov.b64 %0, {%1, %2};" : "=l"(xp) : "f"(xv.x), "f"(xv.y));
        const ulonglong2* wp = (const ulonglong2*)(Wp + k2 * 256 + jg * 16);
        ulonglong2 w0 = wp[0], w1 = wp[1], w2v = wp[2], w3v = wp[3];
        asm("fma.rn.f32x2 %0, %1, %2, %0;" : "+l"(acc[0]) : "l"(xp), "l"(w0.x));
        asm("fma.rn.f32x2 %0, %1, %2, %0;" : "+l"(acc[1]) : "l"(xp), "l"(w0.y));
        asm("fma.rn.f32x2 %0, %1, %2, %0;" : "+l"(acc[2]) : "l"(xp), "l"(w1.x));
        asm("fma.rn.f32x2 %0, %1, %2, %0;" : "+l"(acc[3]) : "l"(xp), "l"(w1.y));
        asm("fma.rn.f32x2 %0, %1, %2, %0;" : "+l"(acc[4]) : "l"(xp), "l"(w2v.x));
        asm("fma.rn.f32x2 %0, %1, %2, %0;" : "+l"(acc[5]) : "l"(xp), "l"(w2v.y));
        asm("fma.rn.f32x2 %0, %1, %2, %0;" : "+l"(acc[6]) : "l"(xp), "l"(w3v.x));
        asm("fma.rn.f32x2 %0, %1, %2, %0;" : "+l"(acc[7]) : "l"(xp), "l"(w3v.y));
    }

    float r[8];
#pragma unroll
    for (int i = 0; i < 8; i++) {
        float lo, hi;
        asm("mov.b64 {%0, %1}, %2;" : "=f"(lo), "=f"(hi) : "l"(acc[i]));
        r[i] = lo + hi;
    }
    int gnode = nb + node;
    int jc = jg * 8;
    if (jc < 64) {
#pragma unroll
        for (int i = 0; i < 8; i++) g_Pd[gnode * 64 + jc + i] = r[i] + b1[jc + i];
    } else {
        int jj = jc - 64;
#pragma unroll
        for (int i = 0; i < 8; i++) g_Ps[gnode * 64 + jj + i] = r[i];
    }
}

// ---------------- edge kernel: gather -> prelu -> h1@W2 -> prelu -> red.v4 --------
// 256 threads = 256 edges per block. Warp-cooperative coalesced gather staged in
// smem, then per-thread 64x64 dot: LDS.128 weight loads feeding 2x fma.rn.f32x2.
__global__ void __launch_bounds__(256, 2) k_edge(const void* eiv,
                                                 const float* __restrict__ W2,
                                                 const float* __restrict__ b2,
                                                 const float* __restrict__ A1,
                                                 const float* __restrict__ A2) {
    extern __shared__ float sm[];
    float* w2t = sm;          // 4096 floats: w2t[j*64+k] = W2[k][j] (rows 256B, 16B aligned)
    float* b2s = sm + 4096;   // 64
    float* hs  = sm + 4160;   // 8 warps * 32 edges * 66 floats

    int t = threadIdx.x;
    for (int idx = t; idx < 4096; idx += 256) {
        int j = idx & 63, k = idx >> 6;
        w2t[j * 64 + k] = W2[k * 64 + j];
    }
    if (t < 64) b2s[t] = b2[t];
    float a1 = A1[0], a2 = A2[0];

    int e = blockIdx.x * 256 + t;           // grid = NE/256 exactly
    long long my_src, my_dst;
    if (g_is64) {
        const long long* ei = (const long long*)eiv;
        my_src = ei[e];
        my_dst = ei[NE + e];
    } else {
        const int* ei = (const int*)eiv;
        my_src = (long long)ei[e];
        my_dst = (long long)ei[NE + e];
    }
    __syncthreads();

    int lane = t & 31;
    float* hsw = hs + (t >> 5) * (32 * 66);

    // Cooperative gather: whole warp loads one edge's 64-wide Pd[dst]+Ps[src]
    // coalesced, applies prelu, stages to smem.
#pragma unroll 1
    for (int ee = 0; ee < 32; ee++) {
        long long d = __shfl_sync(0xffffffffu, my_dst, ee);
        long long s = __shfl_sync(0xffffffffu, my_src, ee);
        const float2* pd2 = (const float2*)(g_Pd + d * 64);
        const float2* ps2 = (const float2*)(g_Ps + s * 64);
        float2 a = pd2[lane];
        float2 b = ps2[lane];
        float v0 = prelu(a.x + b.x, a1);
        float v1 = prelu(a.y + b.y, a1);
        ((float2*)(hsw + ee * 66))[lane] = make_float2(v0, v1);
    }
    __syncwarp();

    // Pull this thread's h1 row into packed f32x2 registers (32 LDS.64, conflict-free).
    unsigned long long hp[32];
    const float2* hrow = (const float2*)(hsw + lane * 66);
#pragma unroll
    for (int k2 = 0; k2 < 32; k2++) {
        float2 v = hrow[k2];
        asm("mov.b64 %0, {%1, %2};" : "=l"(hp[k2]) : "f"(v.x), "f"(v.y));
    }

    float* aggp = g_agg + my_dst * 64;
#pragma unroll 1
    for (int j4 = 0; j4 < 16; j4++) {
        float r[4];
#pragma unroll
        for (int jj = 0; jj < 4; jj++) {
            int j = j4 * 4 + jj;
            const ulonglong2* w = (const ulonglong2*)(w2t + j * 64);
            unsigned long long acc0 = 0ULL, acc1 = 0ULL;
#pragma unroll
            for (int k4 = 0; k4 < 16; k4++) {
                ulonglong2 wv = w[k4];   // LDS.128, warp-uniform broadcast
                asm("fma.rn.f32x2 %0, %1, %2, %0;" : "+l"(acc0) : "l"(hp[2 * k4]),     "l"(wv.x));
                asm("fma.rn.f32x2 %0, %1, %2, %0;" : "+l"(acc1) : "l"(hp[2 * k4 + 1]), "l"(wv.y));
            }
            float l0, h0, l1, h1;
            asm("mov.b64 {%0, %1}, %2;" : "=f"(l0), "=f"(h0) : "l"(acc0));
            asm("mov.b64 {%0, %1}, %2;" : "=f"(l1), "=f"(h1) : "l"(acc1));
            r[jj] = prelu((l0 + l1) + (h0 + h1) + b2s[j], a2);
        }
        asm volatile("red.global.add.v4.f32 [%0], {%1, %2, %3, %4};" ::
                     "l"(aggp + j4 * 4), "f"(r[0]), "f"(r[1]), "f"(r[2]), "f"(r[3]));
    }
}

// ---------------- node MLP + block prelu + BN partial stats (packed weights) ------
// block = 256 threads, 32 nodes/block. Weights pre-packed as k-pairs; inner loop:
// 1 LDS.64 + 4 LDS.128 + 8 FFMA2 per k2.
__global__ void __launch_bounds__(256) k_node(const float* __restrict__ x,
                                              const float* __restrict__ W3,
                                              const float* __restrict__ b3,
                                              const float* __restrict__ A3,
                                              const float* __restrict__ W4,
                                              const float* __restrict__ b4,
                                              const float* __restrict__ Ablk) {
    extern __shared__ float sm[];
    float* ms  = sm;                         // 32*130 = 4160
    float* W3p = sm + 4160;                  // 8192: [(k/2)*128 + j*2 + (k&1)]
    float* W4p = sm + 4160 + 8192;           // 4096: same packing, k<64
    float* z1s = sm + 4160 + 8192 + 4096;    // 32*66 = 2112

    int t = threadIdx.x;
    int nb = blockIdx.x * 32;
    for (int idx = t; idx < 8192; idx += 256) {
        int k = idx >> 6, j = idx & 63;
        W3p[(k >> 1) * 128 + j * 2 + (k & 1)] = W3[idx];
    }
    for (int idx = t; idx < 4096; idx += 256) {
        int k = idx >> 6, j = idx & 63;
        W4p[(k >> 1) * 128 + j * 2 + (k & 1)] = W4[idx];
    }
    for (int idx = t; idx < 2048; idx += 256) {
        int n = idx >> 6, k = idx & 63;
        ms[n * 130 + k]      = x[(nb + n) * 64 + k];
        ms[n * 130 + 64 + k] = g_agg[(nb + n) * 64 + k];
    }
    float a3 = A3[0], ab = Ablk[0];
    __syncthreads();

    int node = t & 31;
    int jg   = t >> 5;   // 0..7
    unsigned long long acc[8];
#pragma unroll
    for (int i = 0; i < 8; i++) acc[i] = 0ULL;

    const float2* mrow = (const float2*)(ms + node * 130);
#pragma unroll 8
    for (int k2 = 0; k2 < 64; k2++) {
        float2 mv = mrow[k2];
        unsigned long long mp;
        asm("mov.b64 %0, {%1, %2};" : "=l"(mp) : "f"(mv.x), "f"(mv.y));
        const ulonglong2* wp = (const ulonglong2*)(W3p + k2 * 128 + jg * 16);
        ulonglong2 w0 = wp[0], w1 = wp[1], w2v = wp[2], w3v = wp[3];
        asm("fma.rn.f32x2 %0, %1, %2, %0;" : "+l"(acc[0]) : "l"(mp), "l"(w0.x));
        asm("fma.rn.f32x2 %0, %1, %2, %0;" : "+l"(acc[1]) : "l"(mp), "l"(w0.y));
        asm("fma.rn.f32x2 %0, %1, %2, %0;" : "+l"(acc[2]) : "l"(mp), "l"(w1.x));
        asm("fma.rn.f32x2 %0, %1, %2, %0;" : "+l"(acc[3]) : "l"(mp), "l"(w1.y));
        asm("fma.rn.f32x2 %0, %1, %2, %0;" : "+l"(acc[4]) : "l"(mp), "l"(w2v.x));
        asm("fma.rn.f32x2 %0, %1, %2, %0;" : "+l"(acc[5]) : "l"(mp), "l"(w2v.y));
        asm("fma.rn.f32x2 %0, %1, %2, %0;" : "+l"(acc[6]) : "l"(mp), "l"(w3v.x));
        asm("fma.rn.f32x2 %0, %1, %2, %0;" : "+l"(acc[7]) : "l"(mp), "l"(w3v.y));
    }
    {
        float2* zrow = (float2*)(z1s + node * 66);
#pragma unroll
        for (int i2 = 0; i2 < 4; i2++) {
            float l0, h0, l1, h1;
            asm("mov.b64 {%0, %1}, %2;" : "=f"(l0), "=f"(h0) : "l"(acc[2 * i2]));
            asm("mov.b64 {%0, %1}, %2;" : "=f"(l1), "=f"(h1) : "l"(acc[2 * i2 + 1]));
            int j = jg * 8 + 2 * i2;
            zrow[jg * 4 + i2] = make_float2(prelu(l0 + h0 + b3[j], a3),
                                            prelu(l1 + h1 + b3[j + 1], a3));
        }
    }
    __syncthreads();

#pragma unroll
    for (int i = 0; i < 8; i++) acc[i] = 0ULL;
    const float2* zr = (const float2*)(z1s + node * 66);
#pragma unroll 8
    for (int k2 = 0; k2 < 32; k2++) {
        float2 zv = zr[k2];
        unsigned long long zpk;
        asm("mov.b64 %0, {%1, %2};" : "=l"(zpk) : "f"(zv.x), "f"(zv.y));
        const ulonglong2* wp = (const ulonglong2*)(W4p + k2 * 128 + jg * 16);
        ulonglong2 w0 = wp[0], w1 = wp[1], w2v = wp[2], w3v = wp[3];
        asm("fma.rn.f32x2 %0, %1, %2, %0;" : "+l"(acc[0]) : "l"(zpk), "l"(w0.x));
        asm("fma.rn.f32x2 %0, %1, %2, %0;" : "+l"(acc[1]) : "l"(zpk), "l"(w0.y));
        asm("fma.rn.f32x2 %0, %1, %2, %0;" : "+l"(acc[2]) : "l"(zpk), "l"(w1.x));
        asm("fma.rn.f32x2 %0, %1, %2, %0;" : "+l"(acc[3]) : "l"(zpk), "l"(w1.y));
        asm("fma.rn.f32x2 %0, %1, %2, %0;" : "+l"(acc[4]) : "l"(zpk), "l"(w2v.x));
        asm("fma.rn.f32x2 %0, %1, %2, %0;" : "+l"(acc[5]) : "l"(zpk), "l"(w2v.y));
        asm("fma.rn.f32x2 %0, %1, %2, %0;" : "+l"(acc[6]) : "l"(zpk), "l"(w3v.x));
        asm("fma.rn.f32x2 %0, %1, %2, %0;" : "+l"(acc[7]) : "l"(zpk), "l"(w3v.y));
    }

    float zp[8], sq[8];
#pragma unroll
    for (int i = 0; i < 8; i++) {
        float lo, hi;
        asm("mov.b64 {%0, %1}, %2;" : "=f"(lo), "=f"(hi) : "l"(acc[i]));
        zp[i] = prelu(lo + hi + b4[jg * 8 + i], ab);
        sq[i] = zp[i] * zp[i];
    }
    int gnode = nb + node;
    float4* o4 = (float4*)(g_zp + gnode * 64 + jg * 8);
    o4[0] = make_float4(zp[0], zp[1], zp[2], zp[3]);
    o4[1] = make_float4(zp[4], zp[5], zp[6], zp[7]);

    // warp butterfly over the 32 nodes (lanes) -> column partial sums
    float s[8];
#pragma unroll
    for (int i = 0; i < 8; i++) s[i] = zp[i];
#pragma unroll
    for (int o = 16; o > 0; o >>= 1) {
#pragma unroll
        for (int i = 0; i < 8; i++) {
            s[i]  += __shfl_xor_sync(0xffffffffu, s[i], o);
            sq[i] += __shfl_xor_sync(0xffffffffu, sq[i], o);
        }
    }
    if ((t & 31) == 0) {
        int j = jg * 8;
#pragma unroll
        for (int i = 0; i < 8; i++) {
            atomicAdd(&g_stats[j + i], s[i]);
            atomicAdd(&g_stats[64 + j + i], sq[i]);
        }
    }
}

// ---------------- BN finalize ----------------
__global__ void __launch_bounds__(256) k_finalize(const float* __restrict__ gamma,
                                                  const float* __restrict__ beta,
                                                  float* __restrict__ out) {
    int i0 = blockIdx.x * blockDim.x + threadIdx.x;
    int stride = gridDim.x * blockDim.x;   // 65536, multiple of 64 -> j fixed per thread
    int j = i0 & 63;
    const float invN = 1.0f / NN;
    float mean  = g_stats[j] * invN;
    float var   = g_stats[64 + j] * invN - mean * mean;
    float scale = rsqrtf(var + 1e-5f) * gamma[j];
    float bias  = beta[j] - mean * scale;
    for (int i = i0; i < NN * 64; i += stride)
        out[i] = g_zp[i] * scale + bias;
}

// ---------------- launch ----------------
extern "C" void kernel_launch(void* const* d_in, const int* in_sizes, int n_in,
                              void* d_out, int out_size) {
    const float* x     = (const float*)d_in[0];
    const void*  ei    = d_in[1];
    const float* W1    = (const float*)d_in[2];
    const float* b1    = (const float*)d_in[3];
    const float* a1    = (const float*)d_in[4];
    const float* W2    = (const float*)d_in[5];
    const float* b2    = (const float*)d_in[6];
    const float* a2    = (const float*)d_in[7];
    const float* W3    = (const float*)d_in[8];
    const float* b3    = (const float*)d_in[9];
    const float* a3    = (const float*)d_in[10];
    const float* W4    = (const float*)d_in[11];
    const float* b4    = (const float*)d_in[12];
    const float* ablk  = (const float*)d_in[13];
    const float* gamma = (const float*)d_in[14];
    const float* beta  = (const float*)d_in[15];
    float* out = (float*)d_out;

    const int EDGE_SMEM = (4160 + 8 * 32 * 66) * 4;                  // 84224 B
    const int NODE_SMEM = (4160 + 8192 + 4096 + 32 * 66) * 4;        // 74240 B
    cudaFuncSetAttribute(k_edge, cudaFuncAttributeMaxDynamicSharedMemorySize, EDGE_SMEM);
    cudaFuncSetAttribute(k_node, cudaFuncAttributeMaxDynamicSharedMemorySize, NODE_SMEM);

    k_detect<<<1, 32>>>((const long long*)ei);
    k_zero<<<2048, 256>>>();
    k_node_pre<<<NN / 16, 256>>>(x, W1, b1);                  // 6250 blocks (exact)
    k_edge<<<NE / 256, 256, EDGE_SMEM>>>(ei, W2, b2, a1, a2); // 6250 blocks (exact)
    k_node<<<NN / 32, 256, NODE_SMEM>>>(x, W3, b3, a3, W4, b4, ablk); // 3125 blocks (exact)
    k_finalize<<<256, 256>>>(gamma, beta, out);
}